// round 7
// baseline (speedup 1.0000x reference)
#include <cuda_runtime.h>
#include <cuda_fp16.h>
#include <cstdint>
#include <cstddef>

// B=32, T=64, H=1024. fp16 operands / fp32 accum everywhere.
#define HD 1024
#define BB 32
#define TT 64
#define G4 4096
#define BT 2048

// ---------------- static device buffers ----------------
__device__ __align__(1024) __half g_Xa   [BT * 2048];
__device__ __align__(1024) __half g_Xm   [BT * 2048];
__device__ __align__(1024) __half g_Wih1a[G4 * 2048];
__device__ __align__(1024) __half g_Wih1m[G4 * 2048];
__device__ __align__(1024) __half g_Whh1a[G4 * HD];
__device__ __align__(1024) __half g_Whh1m[G4 * HD];
__device__ __align__(1024) __half g_Wih2a[G4 * HD];
__device__ __align__(1024) __half g_Wih2m[G4 * HD];
__device__ __align__(1024) __half g_Whh2a[G4 * HD];
__device__ __align__(1024) __half g_Whh2m[G4 * HD];
__device__ __align__(1024) __half g_Wg   [HD * 2048];
__device__ __align__(1024) __half g_Wa   [HD * HD];
__device__ __align__(1024) __half g_Wm   [HD * HD];

__device__ __align__(1024) float  g_X1a[(size_t)BT * G4];
__device__ __align__(1024) float  g_X1m[(size_t)BT * G4];
__device__ float g_bias1a[G4], g_bias1m[G4], g_bias2a[G4], g_bias2m[G4];

__device__ __align__(1024) __half g_h1a[2][BB * HD];
__device__ __align__(1024) __half g_h1m[2][BB * HD];
__device__ __align__(1024) __half g_h2a[BB * HD];
__device__ __align__(1024) __half g_h2m[BB * HD];
__device__ __align__(1024) float  g_c1a[BB * HD], g_c1m[BB * HD];
__device__ __align__(1024) float  g_c2a[BB * HD], g_c2m[BB * HD];
__device__ __align__(1024) float  g_part2a[BB * G4], g_part2m[BB * G4];

__device__ __align__(1024) __half g_Hcat[BT * 2048];
__device__ __align__(1024) float  g_Sa[BT * HD], g_Sm[BT * HD], g_Gl[BT * HD];

// ---------------- helpers ----------------
__device__ __forceinline__ float sigf(float x) { return 1.f / (1.f + expf(-x)); }

__device__ __forceinline__ void cp8(void* s, const void* g) {
    uint32_t sa = (uint32_t)__cvta_generic_to_shared(s);
    asm volatile("cp.async.ca.shared.global [%0], [%1], 8;" :: "r"(sa), "l"(g));
}

__device__ __forceinline__ void mma16816(float* d, const uint32_t* a, const uint32_t* b) {
    asm volatile(
        "mma.sync.aligned.m16n8k16.row.col.f32.f16.f16.f32 "
        "{%0,%1,%2,%3}, {%4,%5,%6,%7}, {%8,%9}, {%0,%1,%2,%3};"
        : "+f"(d[0]), "+f"(d[1]), "+f"(d[2]), "+f"(d[3])
        : "r"(a[0]), "r"(a[1]), "r"(a[2]), "r"(a[3]), "r"(b[0]), "r"(b[1]));
}

// ---------------- generic CTA GEMM ----------------
// C[BM,BN] += A[BM,K](row-major,lda) @ Bw(rows,K)^T.  256 threads, warps 2x4.
// GATEMAP: weight row = (n>>4)*1024 + brow0 + (n&15); else brow0 + n.
#define BKC 32
#define SK  40
#define SKW 20

template<int BM, int BN, int MI, int NI, bool GATEMAP>
__device__ __forceinline__ void run_gemm(
    const __half* __restrict__ A, int lda,
    const __half* __restrict__ Bw, int ldb, int brow0,
    int K, __half* sA, __half* sB, float (*acc)[4])
{
    const int tid  = threadIdx.x;
    const int warp = tid >> 5, lane = tid & 31;
    const int wm = warp >> 2, wn = warp & 3;
    const int grp = lane >> 2, tig = lane & 3;

    auto load_tile = [&](int kt, int buf) {
        const __half* Ag = A + kt * BKC;
        __half* sa = sA + buf * BM * SK;
        for (int idx = tid; idx < BM * 8; idx += 256) {
            int r = idx >> 3, c = idx & 7;
            cp8(sa + r * SK + c * 4, Ag + (size_t)r * lda + c * 4);
        }
        const __half* Bg = Bw + kt * BKC;
        __half* sb = sB + buf * BN * SK;
        for (int idx = tid; idx < BN * 8; idx += 256) {
            int r = idx >> 3, c = idx & 7;
            int wr = GATEMAP ? (((r >> 4) << 10) + brow0 + (r & 15)) : (brow0 + r);
            cp8(sb + r * SK + c * 4, Bg + (size_t)wr * ldb + c * 4);
        }
        asm volatile("cp.async.commit_group;" ::: "memory");
    };

    const int KT = K / BKC;
    load_tile(0, 0);
    for (int kt = 0; kt < KT; kt++) {
        const int buf = kt & 1;
        if (kt + 1 < KT) {
            load_tile(kt + 1, buf ^ 1);
            asm volatile("cp.async.wait_group 1;" ::: "memory");
        } else {
            asm volatile("cp.async.wait_group 0;" ::: "memory");
        }
        __syncthreads();
        const uint32_t* wA = (const uint32_t*)(sA + buf * BM * SK);
        const uint32_t* wB = (const uint32_t*)(sB + buf * BN * SK);
        #pragma unroll
        for (int kk = 0; kk < 2; kk++) {
            uint32_t af[MI][4], bf[NI][2];
            #pragma unroll
            for (int mi = 0; mi < MI; mi++) {
                int r = wm * (MI * 16) + mi * 16 + grp;
                int base = r * SKW + kk * 8 + tig;
                af[mi][0] = wA[base];
                af[mi][1] = wA[base + 8 * SKW];
                af[mi][2] = wA[base + 4];
                af[mi][3] = wA[base + 8 * SKW + 4];
            }
            #pragma unroll
            for (int ni = 0; ni < NI; ni++) {
                int rb = wn * (NI * 8) + ni * 8 + grp;
                int base = rb * SKW + kk * 8 + tig;
                bf[ni][0] = wB[base];
                bf[ni][1] = wB[base + 4];
            }
            #pragma unroll
            for (int mi = 0; mi < MI; mi++)
                #pragma unroll
                for (int ni = 0; ni < NI; ni++)
                    mma16816(acc[mi * NI + ni], af[mi], bf[ni]);
        }
        __syncthreads();
    }
}

// ---------------- big GEMMs: 0 X1a, 1 X1m, 2 Sa, 3 Sm, 4 Gl ----------------
__global__ void __launch_bounds__(256) gemm_big(int which)
{
    __shared__ __align__(16) __half sA[2 * 128 * SK];
    __shared__ __align__(16) __half sB[2 * 128 * SK];
    const __half *A, *Bw;
    float* C;
    const float* bias = nullptr;
    int lda, ldb, K, ldc;
    const int n0 = blockIdx.x * 128, m0 = blockIdx.y * 128;
    switch (which) {
        case 0: A = g_Xa;        lda = 2048; Bw = g_Wih1a; ldb = 2048; K = 2048; C = g_X1a; ldc = G4; bias = g_bias1a; break;
        case 1: A = g_Xm;        lda = 2048; Bw = g_Wih1m; ldb = 2048; K = 2048; C = g_X1m; ldc = G4; bias = g_bias1m; break;
        case 2: A = g_Hcat;      lda = 2048; Bw = g_Wa;    ldb = HD;   K = HD;   C = g_Sa;  ldc = HD; break;
        case 3: A = g_Hcat + HD; lda = 2048; Bw = g_Wm;    ldb = HD;   K = HD;   C = g_Sm;  ldc = HD; break;
        default:A = g_Hcat;      lda = 2048; Bw = g_Wg;    ldb = 2048; K = 2048; C = g_Gl;  ldc = HD; break;
    }
    float acc[16][4] = {};
    run_gemm<128, 128, 4, 4, false>(A + (size_t)m0 * lda, lda, Bw, ldb, n0, K, sA, sB, acc);

    const int warp = threadIdx.x >> 5, lane = threadIdx.x & 31;
    const int wm = warp >> 2, wn = warp & 3, grp = lane >> 2, tig = lane & 3;
    #pragma unroll
    for (int mi = 0; mi < 4; mi++)
        #pragma unroll
        for (int ni = 0; ni < 4; ni++) {
            int r = m0 + wm * 64 + mi * 16 + grp;
            int c = n0 + wn * 32 + ni * 8 + tig * 2;
            float b0 = 0.f, b1 = 0.f;
            if (bias) { b0 = bias[c]; b1 = bias[c + 1]; }
            float* p = C + (size_t)r * ldc + c;
            p[0] = acc[mi * 4 + ni][0] + b0;
            p[1] = acc[mi * 4 + ni][1] + b1;
            p = C + (size_t)(r + 8) * ldc + c;
            p[0] = acc[mi * 4 + ni][2] + b0;
            p[1] = acc[mi * 4 + ni][3] + b1;
        }
}

// ---------------- sequential P1 ----------------
// cid 0: layer1-a cell, 1: layer1-m cell, 2: layer2-a recurrent partial, 3: layer2-m partial
__global__ void __launch_bounds__(256) p1_kernel(int t)
{
    __shared__ __align__(16) __half sA[2 * 32 * SK];
    __shared__ __align__(16) __half sB[2 * 64 * SK];
    __shared__ float sC[32][64];

    const int cid = blockIdx.x >> 6;
    const int u0  = (blockIdx.x & 63) << 4;
    const int rp  = t & 1, wp = rp ^ 1;

    const __half *A, *Bw;
    switch (cid) {
        case 0:  A = g_h1a[rp]; Bw = g_Whh1a; break;
        case 1:  A = g_h1m[rp]; Bw = g_Whh1m; break;
        case 2:  A = g_h2a;     Bw = g_Whh2a; break;
        default: A = g_h2m;     Bw = g_Whh2m; break;
    }
    float acc[2][4] = {};
    run_gemm<32, 64, 1, 2, true>(A, HD, Bw, HD, u0, HD, sA, sB, acc);

    const int warp = threadIdx.x >> 5, lane = threadIdx.x & 31;
    const int wm = warp >> 2, wn = warp & 3, grp = lane >> 2, tig = lane & 3;
    #pragma unroll
    for (int ni = 0; ni < 2; ni++) {
        int r = wm * 16 + grp, c = wn * 16 + ni * 8 + tig * 2;
        sC[r][c]     = acc[ni][0];  sC[r][c + 1]     = acc[ni][1];
        sC[r + 8][c] = acc[ni][2];  sC[r + 8][c + 1] = acc[ni][3];
    }
    __syncthreads();

    if (cid < 2) {
        const float*  X1 = (cid == 0) ? g_X1a : g_X1m;
        float*        c_ = (cid == 0) ? g_c1a : g_c1m;
        __half*       h_ = (cid == 0) ? g_h1a[wp] : g_h1m[wp];
        for (int idx = threadIdx.x; idx < 32 * 16; idx += 256) {
            int b = idx >> 4, j = idx & 15, u = u0 + j;
            size_t xb = ((size_t)(b * 64 + t)) * G4 + u;
            float i_ = sC[b][j]      + X1[xb];
            float f_ = sC[b][16 + j] + X1[xb + 1024];
            float g_ = sC[b][32 + j] + X1[xb + 2048];
            float o_ = sC[b][48 + j] + X1[xb + 3072];
            float cn = sigf(f_) * c_[b * HD + u] + sigf(i_) * tanhf(g_);
            c_[b * HD + u] = cn;
            h_[b * HD + u] = __float2half_rn(sigf(o_) * tanhf(cn));
        }
    } else {
        float*       P  = (cid == 2) ? g_part2a : g_part2m;
        const float* bi = (cid == 2) ? g_bias2a : g_bias2m;
        for (int idx = threadIdx.x; idx < 32 * 64; idx += 256) {
            int b = idx >> 6, n = idx & 63;
            int col = ((n >> 4) << 10) + u0 + (n & 15);
            P[b * G4 + col] = sC[b][n] + bi[col];
        }
    }
}

// ---------------- sequential P2 ----------------
// cid 0: layer2-a, 1: layer2-m. gates = h1_new @ Wih2^T + partial -> cell2, h2, Hcat.
__global__ void __launch_bounds__(256) p2_kernel(int t)
{
    __shared__ __align__(16) __half sA[2 * 32 * SK];
    __shared__ __align__(16) __half sB[2 * 64 * SK];
    __shared__ float sC[32][64];

    const int cid = blockIdx.x >> 6;
    const int u0  = (blockIdx.x & 63) << 4;
    const int wp  = (t & 1) ^ 1;

    const __half* A  = (cid == 0) ? g_h1a[wp] : g_h1m[wp];
    const __half* Bw = (cid == 0) ? g_Wih2a   : g_Wih2m;
    float acc[2][4] = {};
    run_gemm<32, 64, 1, 2, true>(A, HD, Bw, HD, u0, HD, sA, sB, acc);

    const int warp = threadIdx.x >> 5, lane = threadIdx.x & 31;
    const int wm = warp >> 2, wn = warp & 3, grp = lane >> 2, tig = lane & 3;
    #pragma unroll
    for (int ni = 0; ni < 2; ni++) {
        int r = wm * 16 + grp, c = wn * 16 + ni * 8 + tig * 2;
        sC[r][c]     = acc[ni][0];  sC[r][c + 1]     = acc[ni][1];
        sC[r + 8][c] = acc[ni][2];  sC[r + 8][c + 1] = acc[ni][3];
    }
    __syncthreads();

    const float* P  = (cid == 0) ? g_part2a : g_part2m;
    float*       c_ = (cid == 0) ? g_c2a : g_c2m;
    __half*      h_ = (cid == 0) ? g_h2a : g_h2m;
    const int hoff  = (cid == 0) ? 0 : 1024;
    for (int idx = threadIdx.x; idx < 32 * 16; idx += 256) {
        int b = idx >> 4, j = idx & 15, u = u0 + j;
        size_t pb = (size_t)b * G4 + u;
        float i_ = sC[b][j]      + P[pb];
        float f_ = sC[b][16 + j] + P[pb + 1024];
        float g_ = sC[b][32 + j] + P[pb + 2048];
        float o_ = sC[b][48 + j] + P[pb + 3072];
        float cn = sigf(f_) * c_[b * HD + u] + sigf(i_) * tanhf(g_);
        c_[b * HD + u] = cn;
        __half hv = __float2half_rn(sigf(o_) * tanhf(cn));
        h_[b * HD + u] = hv;
        g_Hcat[(size_t)(b * 64 + t) * 2048 + hoff + u] = hv;
    }
}

// ---------------- utility kernels ----------------
// which selects the fp16 destination symbol in DEVICE code (no
// cudaGetSymbolAddress host calls during graph capture).
__global__ void __launch_bounds__(256) f2h_sel_kernel(const float4* __restrict__ src,
                                                      int which, int n4)
{
    __half* dst;
    switch (which) {
        case 0:  dst = g_Xa;    break;
        case 1:  dst = g_Xm;    break;
        case 2:  dst = g_Wih1a; break;
        case 3:  dst = g_Wih1m; break;
        case 4:  dst = g_Whh1a; break;
        case 5:  dst = g_Whh1m; break;
        case 6:  dst = g_Wih2a; break;
        case 7:  dst = g_Wih2m; break;
        case 8:  dst = g_Whh2a; break;
        case 9:  dst = g_Whh2m; break;
        case 10: dst = g_Wg;    break;
        case 11: dst = g_Wa;    break;
        default: dst = g_Wm;    break;
    }
    int i = blockIdx.x * 256 + threadIdx.x;
    if (i < n4) {
        float4 v = src[i];
        __half2 lo = __floats2half2_rn(v.x, v.y);
        __half2 hi = __floats2half2_rn(v.z, v.w);
        uint2 o;
        o.x = *reinterpret_cast<const uint32_t*>(&lo);
        o.y = *reinterpret_cast<const uint32_t*>(&hi);
        reinterpret_cast<uint2*>(dst)[i] = o;
    }
}

__global__ void __launch_bounds__(256) zero_state_kernel()
{
    int i = blockIdx.x * 256 + threadIdx.x;
    if (i < BB * HD) {
        g_h1a[0][i] = __half(0.f); g_h1a[1][i] = __half(0.f);
        g_h1m[0][i] = __half(0.f); g_h1m[1][i] = __half(0.f);
        g_h2a[i] = __half(0.f);    g_h2m[i] = __half(0.f);
        g_c1a[i] = 0.f; g_c1m[i] = 0.f; g_c2a[i] = 0.f; g_c2m[i] = 0.f;
    }
}

__global__ void __launch_bounds__(256) bias_kernel(
    const float* b1a, const float* b1a2, const float* b1m, const float* b1m2,
    const float* b2a, const float* b2a2, const float* b2m, const float* b2m2)
{
    int i = blockIdx.x * 256 + threadIdx.x;
    if (i < G4) {
        g_bias1a[i] = b1a[i] + b1a2[i];
        g_bias1m[i] = b1m[i] + b1m2[i];
        g_bias2a[i] = b2a[i] + b2a2[i];
        g_bias2m[i] = b2m[i] + b2m2[i];
    }
}

__global__ void __launch_bounds__(256) fuse_kernel(
    const float* __restrict__ bg, const float* __restrict__ ba,
    const float* __restrict__ bm, float* __restrict__ out)
{
    int i = blockIdx.x * 256 + threadIdx.x;
    if (i < BT * HD) {
        int h = i & 1023;
        float g = sigf(g_Gl[i] + bg[h]);
        out[i] = g * tanhf(g_Sa[i] + ba[h]) + (1.f - g) * tanhf(g_Sm[i] + bm[h]);
    }
}

// ---------------- host ----------------
extern "C" void kernel_launch(void* const* d_in, const int* in_sizes, int n_in,
                              void* d_out, int out_size)
{
    if (n_in < 24) return;
    const float* in[24];
    for (int i = 0; i < 24; i++) in[i] = (const float*)d_in[i];
    // 0 app, 1 mot, 2-5 1a(Wih,Whh,bih,bhh), 6-9 2a, 10-13 1m, 14-17 2m,
    // 18 Wg, 19 bg, 20 Wa, 21 ba, 22 Wm, 23 bm

    zero_state_kernel<<<(BB * HD + 255) / 256, 256>>>();

    // fp32 -> fp16 conversions (destination chosen device-side by `which`)
    struct Cv { int src; int which; int n; };
    const Cv cv[] = {
        {0,  0,  BT * 2048}, {1,  1,  BT * 2048},
        {2,  2,  G4 * 2048}, {10, 3,  G4 * 2048},
        {3,  4,  G4 * HD},   {11, 5,  G4 * HD},
        {6,  6,  G4 * HD},   {14, 7,  G4 * HD},
        {7,  8,  G4 * HD},   {15, 9,  G4 * HD},
        {18, 10, HD * 2048}, {20, 11, HD * HD}, {22, 12, HD * HD},
    };
    for (const auto& c : cv) {
        int n4 = c.n / 4;
        f2h_sel_kernel<<<(n4 + 255) / 256, 256>>>((const float4*)in[c.src],
                                                  c.which, n4);
    }

    bias_kernel<<<(G4 + 255) / 256, 256>>>(in[4], in[5], in[12], in[13],
                                           in[8], in[9], in[16], in[17]);

    // big input-projection GEMMs: M=2048, N=4096
    gemm_big<<<dim3(32, 16), 256>>>(0);
    gemm_big<<<dim3(32, 16), 256>>>(1);

    // sequential recurrence
    for (int t = 0; t < TT; t++) {
        p1_kernel<<<256, 256>>>(t);
        p2_kernel<<<128, 256>>>(t);
    }

    // fusion GEMMs: M=2048, N=1024
    gemm_big<<<dim3(8, 16), 256>>>(4);
    gemm_big<<<dim3(8, 16), 256>>>(2);
    gemm_big<<<dim3(8, 16), 256>>>(3);

    fuse_kernel<<<(BT * HD + 255) / 256, 256>>>(in[19], in[21], in[23], (float*)d_out);
}

// round 8
// speedup vs baseline: 1.0425x; 1.0425x over previous
#include <cuda_runtime.h>
#include <cuda_fp16.h>
#include <cstdint>
#include <cstddef>

// B=32, T=64, H=1024. fp16 operands / fp32 accum everywhere.
#define HD 1024
#define BB 32
#define TT 64
#define G4 4096
#define BT 2048

// ---------------- static device buffers ----------------
__device__ __align__(1024) __half g_Xa   [BT * 2048];
__device__ __align__(1024) __half g_Xm   [BT * 2048];
__device__ __align__(1024) __half g_Wih1a[G4 * 2048];
__device__ __align__(1024) __half g_Wih1m[G4 * 2048];
__device__ __align__(1024) __half g_Whh1a[G4 * HD];
__device__ __align__(1024) __half g_Whh1m[G4 * HD];
__device__ __align__(1024) __half g_Wih2a[G4 * HD];
__device__ __align__(1024) __half g_Wih2m[G4 * HD];
__device__ __align__(1024) __half g_Whh2a[G4 * HD];
__device__ __align__(1024) __half g_Whh2m[G4 * HD];
__device__ __align__(1024) __half g_Wg   [HD * 2048];
__device__ __align__(1024) __half g_Wa   [HD * HD];
__device__ __align__(1024) __half g_Wm   [HD * HD];

__device__ __align__(1024) float  g_X1a[(size_t)BT * G4];
__device__ __align__(1024) float  g_X1m[(size_t)BT * G4];
__device__ float g_bias1a[G4], g_bias1m[G4], g_bias2a[G4], g_bias2m[G4];

__device__ __align__(1024) __half g_h1a[2][BB * HD];
__device__ __align__(1024) __half g_h1m[2][BB * HD];
__device__ __align__(1024) __half g_h2a[BB * HD];
__device__ __align__(1024) __half g_h2m[BB * HD];
__device__ __align__(1024) float  g_c1a[BB * HD], g_c1m[BB * HD];
__device__ __align__(1024) float  g_c2a[BB * HD], g_c2m[BB * HD];
__device__ __align__(1024) float  g_part2a[BB * G4], g_part2m[BB * G4];

__device__ __align__(1024) __half g_Hcat[BT * 2048];
__device__ __align__(1024) float  g_Sa[BT * HD], g_Sm[BT * HD], g_Gl[BT * HD];

// ---------------- helpers ----------------
__device__ __forceinline__ float sigf(float x) { return 1.f / (1.f + expf(-x)); }

__device__ __forceinline__ void cp8(void* s, const void* g) {
    uint32_t sa = (uint32_t)__cvta_generic_to_shared(s);
    asm volatile("cp.async.ca.shared.global [%0], [%1], 8;" :: "r"(sa), "l"(g));
}

__device__ __forceinline__ void mma16816(float* d, const uint32_t* a, const uint32_t* b) {
    asm volatile(
        "mma.sync.aligned.m16n8k16.row.col.f32.f16.f16.f32 "
        "{%0,%1,%2,%3}, {%4,%5,%6,%7}, {%8,%9}, {%0,%1,%2,%3};"
        : "+f"(d[0]), "+f"(d[1]), "+f"(d[2]), "+f"(d[3])
        : "r"(a[0]), "r"(a[1]), "r"(a[2]), "r"(a[3]), "r"(b[0]), "r"(b[1]));
}

// ---------------- generic CTA GEMM (big tiles) ----------------
#define BKC 32
#define SK  40
#define SKW 20

template<int BM, int BN, int MI, int NI>
__device__ __forceinline__ void run_gemm(
    const __half* __restrict__ A, int lda,
    const __half* __restrict__ Bw, int ldb, int brow0,
    int K, __half* sA, __half* sB, float (*acc)[4])
{
    const int tid  = threadIdx.x;
    const int warp = tid >> 5, lane = tid & 31;
    const int wm = warp >> 2, wn = warp & 3;
    const int grp = lane >> 2, tig = lane & 3;

    auto load_tile = [&](int kt, int buf) {
        const __half* Ag = A + kt * BKC;
        __half* sa = sA + buf * BM * SK;
        for (int idx = tid; idx < BM * 8; idx += 256) {
            int r = idx >> 3, c = idx & 7;
            cp8(sa + r * SK + c * 4, Ag + (size_t)r * lda + c * 4);
        }
        const __half* Bg = Bw + kt * BKC;
        __half* sb = sB + buf * BN * SK;
        for (int idx = tid; idx < BN * 8; idx += 256) {
            int r = idx >> 3, c = idx & 7;
            cp8(sb + r * SK + c * 4, Bg + (size_t)(brow0 + r) * ldb + c * 4);
        }
        asm volatile("cp.async.commit_group;" ::: "memory");
    };

    const int KT = K / BKC;
    load_tile(0, 0);
    for (int kt = 0; kt < KT; kt++) {
        const int buf = kt & 1;
        if (kt + 1 < KT) {
            load_tile(kt + 1, buf ^ 1);
            asm volatile("cp.async.wait_group 1;" ::: "memory");
        } else {
            asm volatile("cp.async.wait_group 0;" ::: "memory");
        }
        __syncthreads();
        const uint32_t* wA = (const uint32_t*)(sA + buf * BM * SK);
        const uint32_t* wB = (const uint32_t*)(sB + buf * BN * SK);
        #pragma unroll
        for (int kk = 0; kk < 2; kk++) {
            uint32_t af[MI][4], bf[NI][2];
            #pragma unroll
            for (int mi = 0; mi < MI; mi++) {
                int r = wm * (MI * 16) + mi * 16 + grp;
                int base = r * SKW + kk * 8 + tig;
                af[mi][0] = wA[base];
                af[mi][1] = wA[base + 8 * SKW];
                af[mi][2] = wA[base + 4];
                af[mi][3] = wA[base + 8 * SKW + 4];
            }
            #pragma unroll
            for (int ni = 0; ni < NI; ni++) {
                int rb = wn * (NI * 8) + ni * 8 + grp;
                int base = rb * SKW + kk * 8 + tig;
                bf[ni][0] = wB[base];
                bf[ni][1] = wB[base + 4];
            }
            #pragma unroll
            for (int mi = 0; mi < MI; mi++)
                #pragma unroll
                for (int ni = 0; ni < NI; ni++)
                    mma16816(acc[mi * NI + ni], af[mi], bf[ni]);
        }
        __syncthreads();
    }
}

// ---------------- big GEMMs: 0 X1a, 1 X1m, 2 Sa, 3 Sm, 4 Gl ----------------
__global__ void __launch_bounds__(256) gemm_big(int which)
{
    __shared__ __align__(16) __half sA[2 * 128 * SK];
    __shared__ __align__(16) __half sB[2 * 128 * SK];
    const __half *A, *Bw;
    float* C;
    const float* bias = nullptr;
    int lda, ldb, K, ldc;
    const int n0 = blockIdx.x * 128, m0 = blockIdx.y * 128;
    switch (which) {
        case 0: A = g_Xa;        lda = 2048; Bw = g_Wih1a; ldb = 2048; K = 2048; C = g_X1a; ldc = G4; bias = g_bias1a; break;
        case 1: A = g_Xm;        lda = 2048; Bw = g_Wih1m; ldb = 2048; K = 2048; C = g_X1m; ldc = G4; bias = g_bias1m; break;
        case 2: A = g_Hcat;      lda = 2048; Bw = g_Wa;    ldb = HD;   K = HD;   C = g_Sa;  ldc = HD; break;
        case 3: A = g_Hcat + HD; lda = 2048; Bw = g_Wm;    ldb = HD;   K = HD;   C = g_Sm;  ldc = HD; break;
        default:A = g_Hcat;      lda = 2048; Bw = g_Wg;    ldb = 2048; K = 2048; C = g_Gl;  ldc = HD; break;
    }
    float acc[16][4] = {};
    run_gemm<128, 128, 4, 4>(A + (size_t)m0 * lda, lda, Bw, ldb, n0, K, sA, sB, acc);

    const int warp = threadIdx.x >> 5, lane = threadIdx.x & 31;
    const int wm = warp >> 2, wn = warp & 3, grp = lane >> 2, tig = lane & 3;
    #pragma unroll
    for (int mi = 0; mi < 4; mi++)
        #pragma unroll
        for (int ni = 0; ni < 4; ni++) {
            int r = m0 + wm * 64 + mi * 16 + grp;
            int c = n0 + wn * 32 + ni * 8 + tig * 2;
            float b0 = 0.f, b1 = 0.f;
            if (bias) { b0 = bias[c]; b1 = bias[c + 1]; }
            float* p = C + (size_t)r * ldc + c;
            p[0] = acc[mi * 4 + ni][0] + b0;
            p[1] = acc[mi * 4 + ni][1] + b1;
            p = C + (size_t)(r + 8) * ldc + c;
            p[0] = acc[mi * 4 + ni][2] + b0;
            p[1] = acc[mi * 4 + ni][3] + b1;
        }
}

// ---------------- sequential-core GEMM: BM=32, BN=128, BK=64 ----------------
// A[32,1024] row-major @ Bw^T where weight row = gate*1024 + u0 + unit,
// gate = n>>5, unit = n&31, n in [0,128).  256 threads, warps 2x4, MI=1 NI=4.
// Returns acc[4][4] per warp; gate-major layout in sC: col n = gate*32 + j.
#define BK2  64
#define SK2  72
#define SK2W 36
#define SEQ_SMEM (2*32*SK2*2 + 2*128*SK2*2)   // 9216 + 36864 = 46080 bytes

__device__ __forceinline__ void run_gemm_seq(
    const __half* __restrict__ A,
    const __half* __restrict__ Bw, int u0,
    char* smem_raw, float (*acc)[4])
{
    __half* sA = (__half*)smem_raw;                   // 2 x 32 x SK2
    __half* sB = (__half*)(smem_raw + 2*32*SK2*2);    // 2 x 128 x SK2

    const int tid  = threadIdx.x;
    const int warp = tid >> 5, lane = tid & 31;
    const int wm = warp >> 2, wn = warp & 3;
    const int grp = lane >> 2, tig = lane & 3;

    auto load_tile = [&](int kt, int buf) {
        const int k0 = kt * BK2;
        // A: 32 rows x 16 chunks(8B) = 512;  B: 128 rows x 16 chunks = 2048
        __half* sa = sA + buf * 32 * SK2;
        __half* sb = sB + buf * 128 * SK2;
        for (int idx = tid; idx < 2560; idx += 256) {
            if (idx < 512) {
                int r = idx >> 4, c = idx & 15;
                cp8(sa + r * SK2 + c * 4, A + (size_t)r * HD + k0 + c * 4);
            } else {
                int j = idx - 512;
                int r = j >> 4, c = j & 15;
                int wr = ((r >> 5) << 10) + u0 + (r & 31);
                cp8(sb + r * SK2 + c * 4, Bw + (size_t)wr * HD + k0 + c * 4);
            }
        }
        asm volatile("cp.async.commit_group;" ::: "memory");
    };

    const int KT = HD / BK2;   // 16
    load_tile(0, 0);
    for (int kt = 0; kt < KT; kt++) {
        const int buf = kt & 1;
        if (kt + 1 < KT) {
            load_tile(kt + 1, buf ^ 1);
            asm volatile("cp.async.wait_group 1;" ::: "memory");
        } else {
            asm volatile("cp.async.wait_group 0;" ::: "memory");
        }
        __syncthreads();
        const uint32_t* wA = (const uint32_t*)(sA + buf * 32 * SK2);
        const uint32_t* wB = (const uint32_t*)(sB + buf * 128 * SK2);
        #pragma unroll
        for (int kk = 0; kk < 4; kk++) {
            uint32_t af[4], bf[4][2];
            {
                int r = wm * 16 + grp;
                int base = r * SK2W + kk * 8 + tig;
                af[0] = wA[base];
                af[1] = wA[base + 8 * SK2W];
                af[2] = wA[base + 4];
                af[3] = wA[base + 8 * SK2W + 4];
            }
            #pragma unroll
            for (int ni = 0; ni < 4; ni++) {
                int rb = wn * 32 + ni * 8 + grp;
                int base = rb * SK2W + kk * 8 + tig;
                bf[ni][0] = wB[base];
                bf[ni][1] = wB[base + 4];
            }
            #pragma unroll
            for (int ni = 0; ni < 4; ni++)
                mma16816(acc[ni], af, bf[ni]);
        }
        __syncthreads();
    }
}

// store per-warp acc into sC[32][128] (aliases the pipe buffers; callers sync)
__device__ __forceinline__ void seq_store_sC(float (*sC)[128], float (*acc)[4])
{
    const int warp = threadIdx.x >> 5, lane = threadIdx.x & 31;
    const int wm = warp >> 2, wn = warp & 3, grp = lane >> 2, tig = lane & 3;
    #pragma unroll
    for (int ni = 0; ni < 4; ni++) {
        int r = wm * 16 + grp, c = wn * 32 + ni * 8 + tig * 2;
        sC[r][c]     = acc[ni][0];  sC[r][c + 1]     = acc[ni][1];
        sC[r + 8][c] = acc[ni][2];  sC[r + 8][c + 1] = acc[ni][3];
    }
}

// ---------------- sequential P1 (128 CTAs) ----------------
// cid = bx>>5 (0 l1-a cell, 1 l1-m cell, 2 l2-a partial, 3 l2-m partial)
// u0 = (bx&31)*32 : 32 hidden units per CTA.
__global__ void __launch_bounds__(256) p1_kernel(int t)
{
    __shared__ __align__(16) char smem_raw[SEQ_SMEM];

    const int cid = blockIdx.x >> 5;
    const int u0  = (blockIdx.x & 31) << 5;
    const int rp  = t & 1, wp = rp ^ 1;

    const __half *A, *Bw;
    switch (cid) {
        case 0:  A = g_h1a[rp]; Bw = g_Whh1a; break;
        case 1:  A = g_h1m[rp]; Bw = g_Whh1m; break;
        case 2:  A = g_h2a;     Bw = g_Whh2a; break;
        default: A = g_h2m;     Bw = g_Whh2m; break;
    }
    float acc[4][4] = {};
    run_gemm_seq(A, Bw, u0, smem_raw, acc);

    float (*sC)[128] = (float(*)[128])smem_raw;
    seq_store_sC(sC, acc);
    __syncthreads();

    if (cid < 2) {
        const float*  X1 = (cid == 0) ? g_X1a : g_X1m;
        float*        c_ = (cid == 0) ? g_c1a : g_c1m;
        __half*       h_ = (cid == 0) ? g_h1a[wp] : g_h1m[wp];
        for (int idx = threadIdx.x; idx < 32 * 32; idx += 256) {
            int b = idx >> 5, j = idx & 31, u = u0 + j;
            size_t xb = ((size_t)(b * 64 + t)) * G4 + u;
            float i_ = sC[b][j]      + X1[xb];
            float f_ = sC[b][32 + j] + X1[xb + 1024];
            float g_ = sC[b][64 + j] + X1[xb + 2048];
            float o_ = sC[b][96 + j] + X1[xb + 3072];
            float cn = sigf(f_) * c_[b * HD + u] + sigf(i_) * tanhf(g_);
            c_[b * HD + u] = cn;
            h_[b * HD + u] = __float2half_rn(sigf(o_) * tanhf(cn));
        }
    } else {
        float*       P  = (cid == 2) ? g_part2a : g_part2m;
        const float* bi = (cid == 2) ? g_bias2a : g_bias2m;
        for (int idx = threadIdx.x; idx < 32 * 128; idx += 256) {
            int b = idx >> 7, n = idx & 127;
            int col = ((n >> 5) << 10) + u0 + (n & 31);
            P[b * G4 + col] = sC[b][n] + bi[col];
        }
    }
}

// ---------------- sequential P2 (64 CTAs) ----------------
// cid = bx>>5 (0 l2-a, 1 l2-m); gates = h1_new @ Wih2^T + partial.
__global__ void __launch_bounds__(256) p2_kernel(int t)
{
    __shared__ __align__(16) char smem_raw[SEQ_SMEM];

    const int cid = blockIdx.x >> 5;
    const int u0  = (blockIdx.x & 31) << 5;
    const int wp  = (t & 1) ^ 1;

    const __half* A  = (cid == 0) ? g_h1a[wp] : g_h1m[wp];
    const __half* Bw = (cid == 0) ? g_Wih2a   : g_Wih2m;
    float acc[4][4] = {};
    run_gemm_seq(A, Bw, u0, smem_raw, acc);

    float (*sC)[128] = (float(*)[128])smem_raw;
    seq_store_sC(sC, acc);
    __syncthreads();

    const float* P  = (cid == 0) ? g_part2a : g_part2m;
    float*       c_ = (cid == 0) ? g_c2a : g_c2m;
    __half*      h_ = (cid == 0) ? g_h2a : g_h2m;
    const int hoff  = (cid == 0) ? 0 : 1024;
    for (int idx = threadIdx.x; idx < 32 * 32; idx += 256) {
        int b = idx >> 5, j = idx & 31, u = u0 + j;
        size_t pb = (size_t)b * G4 + u;
        float i_ = sC[b][j]      + P[pb];
        float f_ = sC[b][32 + j] + P[pb + 1024];
        float g_ = sC[b][64 + j] + P[pb + 2048];
        float o_ = sC[b][96 + j] + P[pb + 3072];
        float cn = sigf(f_) * c_[b * HD + u] + sigf(i_) * tanhf(g_);
        c_[b * HD + u] = cn;
        __half hv = __float2half_rn(sigf(o_) * tanhf(cn));
        h_[b * HD + u] = hv;
        g_Hcat[(size_t)(b * 64 + t) * 2048 + hoff + u] = hv;
    }
}

// ---------------- utility kernels ----------------
__global__ void __launch_bounds__(256) f2h_sel_kernel(const float4* __restrict__ src,
                                                      int which, int n4)
{
    __half* dst;
    switch (which) {
        case 0:  dst = g_Xa;    break;
        case 1:  dst = g_Xm;    break;
        case 2:  dst = g_Wih1a; break;
        case 3:  dst = g_Wih1m; break;
        case 4:  dst = g_Whh1a; break;
        case 5:  dst = g_Whh1m; break;
        case 6:  dst = g_Wih2a; break;
        case 7:  dst = g_Wih2m; break;
        case 8:  dst = g_Whh2a; break;
        case 9:  dst = g_Whh2m; break;
        case 10: dst = g_Wg;    break;
        case 11: dst = g_Wa;    break;
        default: dst = g_Wm;    break;
    }
    int i = blockIdx.x * 256 + threadIdx.x;
    if (i < n4) {
        float4 v = src[i];
        __half2 lo = __floats2half2_rn(v.x, v.y);
        __half2 hi = __floats2half2_rn(v.z, v.w);
        uint2 o;
        o.x = *reinterpret_cast<const uint32_t*>(&lo);
        o.y = *reinterpret_cast<const uint32_t*>(&hi);
        reinterpret_cast<uint2*>(dst)[i] = o;
    }
}

__global__ void __launch_bounds__(256) zero_state_kernel()
{
    int i = blockIdx.x * 256 + threadIdx.x;
    if (i < BB * HD) {
        g_h1a[0][i] = __half(0.f); g_h1a[1][i] = __half(0.f);
        g_h1m[0][i] = __half(0.f); g_h1m[1][i] = __half(0.f);
        g_h2a[i] = __half(0.f);    g_h2m[i] = __half(0.f);
        g_c1a[i] = 0.f; g_c1m[i] = 0.f; g_c2a[i] = 0.f; g_c2m[i] = 0.f;
    }
}

__global__ void __launch_bounds__(256) bias_kernel(
    const float* b1a, const float* b1a2, const float* b1m, const float* b1m2,
    const float* b2a, const float* b2a2, const float* b2m, const float* b2m2)
{
    int i = blockIdx.x * 256 + threadIdx.x;
    if (i < G4) {
        g_bias1a[i] = b1a[i] + b1a2[i];
        g_bias1m[i] = b1m[i] + b1m2[i];
        g_bias2a[i] = b2a[i] + b2a2[i];
        g_bias2m[i] = b2m[i] + b2m2[i];
    }
}

__global__ void __launch_bounds__(256) fuse_kernel(
    const float* __restrict__ bg, const float* __restrict__ ba,
    const float* __restrict__ bm, float* __restrict__ out)
{
    int i = blockIdx.x * 256 + threadIdx.x;
    if (i < BT * HD) {
        int h = i & 1023;
        float g = sigf(g_Gl[i] + bg[h]);
        out[i] = g * tanhf(g_Sa[i] + ba[h]) + (1.f - g) * tanhf(g_Sm[i] + bm[h]);
    }
}

// ---------------- host ----------------
extern "C" void kernel_launch(void* const* d_in, const int* in_sizes, int n_in,
                              void* d_out, int out_size)
{
    if (n_in < 24) return;
    const float* in[24];
    for (int i = 0; i < 24; i++) in[i] = (const float*)d_in[i];
    // 0 app, 1 mot, 2-5 1a(Wih,Whh,bih,bhh), 6-9 2a, 10-13 1m, 14-17 2m,
    // 18 Wg, 19 bg, 20 Wa, 21 ba, 22 Wm, 23 bm

    zero_state_kernel<<<(BB * HD + 255) / 256, 256>>>();

    struct Cv { int src; int which; int n; };
    const Cv cv[] = {
        {0,  0,  BT * 2048}, {1,  1,  BT * 2048},
        {2,  2,  G4 * 2048}, {10, 3,  G4 * 2048},
        {3,  4,  G4 * HD},   {11, 5,  G4 * HD},
        {6,  6,  G4 * HD},   {14, 7,  G4 * HD},
        {7,  8,  G4 * HD},   {15, 9,  G4 * HD},
        {18, 10, HD * 2048}, {20, 11, HD * HD}, {22, 12, HD * HD},
    };
    for (const auto& c : cv) {
        int n4 = c.n / 4;
        f2h_sel_kernel<<<(n4 + 255) / 256, 256>>>((const float4*)in[c.src],
                                                  c.which, n4);
    }

    bias_kernel<<<(G4 + 255) / 256, 256>>>(in[4], in[5], in[12], in[13],
                                           in[8], in[9], in[16], in[17]);

    // big input-projection GEMMs: M=2048, N=4096
    gemm_big<<<dim3(32, 16), 256>>>(0);
    gemm_big<<<dim3(32, 16), 256>>>(1);

    // sequential recurrence: p1 = 128 CTAs (one wave), p2 = 64 CTAs
    for (int t = 0; t < TT; t++) {
        p1_kernel<<<128, 256>>>(t);
        p2_kernel<<<64, 256>>>(t);
    }

    // fusion GEMMs: M=2048, N=1024
    gemm_big<<<dim3(8, 16), 256>>>(4);
    gemm_big<<<dim3(8, 16), 256>>>(2);
    gemm_big<<<dim3(8, 16), 256>>>(3);

    fuse_kernel<<<(BT * HD + 255) / 256, 256>>>(in[19], in[21], in[23], (float*)d_out);
}

// round 9
// speedup vs baseline: 1.1086x; 1.0634x over previous
#include <cuda_runtime.h>
#include <cuda_fp16.h>
#include <cstdint>
#include <cstddef>

// B=32, T=64, H=1024. fp16 operands / fp32 accum everywhere.
#define HD 1024
#define BB 32
#define TT 64
#define G4 4096
#define BT 2048

// ---------------- static device buffers ----------------
__device__ __align__(1024) __half g_Xa   [BT * 2048];
__device__ __align__(1024) __half g_Xm   [BT * 2048];
__device__ __align__(1024) __half g_Wih1a[G4 * 2048];
__device__ __align__(1024) __half g_Wih1m[G4 * 2048];
__device__ __align__(1024) __half g_Whh1a[G4 * HD];
__device__ __align__(1024) __half g_Whh1m[G4 * HD];
__device__ __align__(1024) __half g_Wih2a[G4 * HD];
__device__ __align__(1024) __half g_Wih2m[G4 * HD];
__device__ __align__(1024) __half g_Whh2a[G4 * HD];
__device__ __align__(1024) __half g_Whh2m[G4 * HD];
__device__ __align__(1024) __half g_Wg   [HD * 2048];
__device__ __align__(1024) __half g_Wa   [HD * HD];
__device__ __align__(1024) __half g_Wm   [HD * HD];

__device__ __align__(1024) float  g_X1a[(size_t)BT * G4];
__device__ __align__(1024) float  g_X1m[(size_t)BT * G4];
__device__ float g_bias1a[G4], g_bias1m[G4], g_bias2a[G4], g_bias2m[G4];

__device__ __align__(1024) __half g_h1a[2][BB * HD];
__device__ __align__(1024) __half g_h1m[2][BB * HD];
__device__ __align__(1024) __half g_h2a[BB * HD];
__device__ __align__(1024) __half g_h2m[BB * HD];
__device__ __align__(1024) float  g_c1a[BB * HD], g_c1m[BB * HD];
__device__ __align__(1024) float  g_c2a[BB * HD], g_c2m[BB * HD];
__device__ __align__(1024) float  g_part2a[BB * G4], g_part2m[BB * G4];

__device__ __align__(1024) __half g_Hcat[BT * 2048];
__device__ __align__(1024) float  g_Sa[BT * HD], g_Sm[BT * HD], g_Gl[BT * HD];

// device-wide barrier state for the persistent sequential kernel
__device__ int          g_bar_count = 0;
__device__ volatile int g_bar_gen   = 0;

// ---------------- helpers ----------------
__device__ __forceinline__ float sigf(float x) { return 1.f / (1.f + expf(-x)); }

__device__ __forceinline__ void cp8(void* s, const void* g) {
    uint32_t sa = (uint32_t)__cvta_generic_to_shared(s);
    asm volatile("cp.async.ca.shared.global [%0], [%1], 8;" :: "r"(sa), "l"(g));
}

__device__ __forceinline__ void mma16816(float* d, const uint32_t* a, const uint32_t* b) {
    asm volatile(
        "mma.sync.aligned.m16n8k16.row.col.f32.f16.f16.f32 "
        "{%0,%1,%2,%3}, {%4,%5,%6,%7}, {%8,%9}, {%0,%1,%2,%3};"
        : "+f"(d[0]), "+f"(d[1]), "+f"(d[2]), "+f"(d[3])
        : "r"(a[0]), "r"(a[1]), "r"(a[2]), "r"(a[3]), "r"(b[0]), "r"(b[1]));
}

// all-CTA barrier (all CTAs guaranteed resident: grid=128 <= 148 SMs)
__device__ __forceinline__ void gsync(int nblocks) {
    __syncthreads();
    if (threadIdx.x == 0) {
        int gen = g_bar_gen;
        __threadfence();
        if (atomicAdd(&g_bar_count, 1) == nblocks - 1) {
            g_bar_count = 0;
            __threadfence();
            g_bar_gen = gen + 1;
        } else {
            while (g_bar_gen == gen) { __nanosleep(32); }
        }
        __threadfence();
    }
    __syncthreads();
}

// ---------------- generic CTA GEMM (big tiles) ----------------
#define BKC 32
#define SK  40
#define SKW 20

template<int BM, int BN, int MI, int NI>
__device__ __forceinline__ void run_gemm(
    const __half* __restrict__ A, int lda,
    const __half* __restrict__ Bw, int ldb, int brow0,
    int K, __half* sA, __half* sB, float (*acc)[4])
{
    const int tid  = threadIdx.x;
    const int warp = tid >> 5, lane = tid & 31;
    const int wm = warp >> 2, wn = warp & 3;
    const int grp = lane >> 2, tig = lane & 3;

    auto load_tile = [&](int kt, int buf) {
        const __half* Ag = A + kt * BKC;
        __half* sa = sA + buf * BM * SK;
        for (int idx = tid; idx < BM * 8; idx += 256) {
            int r = idx >> 3, c = idx & 7;
            cp8(sa + r * SK + c * 4, Ag + (size_t)r * lda + c * 4);
        }
        const __half* Bg = Bw + kt * BKC;
        __half* sb = sB + buf * BN * SK;
        for (int idx = tid; idx < BN * 8; idx += 256) {
            int r = idx >> 3, c = idx & 7;
            cp8(sb + r * SK + c * 4, Bg + (size_t)(brow0 + r) * ldb + c * 4);
        }
        asm volatile("cp.async.commit_group;" ::: "memory");
    };

    const int KT = K / BKC;
    load_tile(0, 0);
    for (int kt = 0; kt < KT; kt++) {
        const int buf = kt & 1;
        if (kt + 1 < KT) {
            load_tile(kt + 1, buf ^ 1);
            asm volatile("cp.async.wait_group 1;" ::: "memory");
        } else {
            asm volatile("cp.async.wait_group 0;" ::: "memory");
        }
        __syncthreads();
        const uint32_t* wA = (const uint32_t*)(sA + buf * BM * SK);
        const uint32_t* wB = (const uint32_t*)(sB + buf * BN * SK);
        #pragma unroll
        for (int kk = 0; kk < 2; kk++) {
            uint32_t af[MI][4], bf[NI][2];
            #pragma unroll
            for (int mi = 0; mi < MI; mi++) {
                int r = wm * (MI * 16) + mi * 16 + grp;
                int base = r * SKW + kk * 8 + tig;
                af[mi][0] = wA[base];
                af[mi][1] = wA[base + 8 * SKW];
                af[mi][2] = wA[base + 4];
                af[mi][3] = wA[base + 8 * SKW + 4];
            }
            #pragma unroll
            for (int ni = 0; ni < NI; ni++) {
                int rb = wn * (NI * 8) + ni * 8 + grp;
                int base = rb * SKW + kk * 8 + tig;
                bf[ni][0] = wB[base];
                bf[ni][1] = wB[base + 4];
            }
            #pragma unroll
            for (int mi = 0; mi < MI; mi++)
                #pragma unroll
                for (int ni = 0; ni < NI; ni++)
                    mma16816(acc[mi * NI + ni], af[mi], bf[ni]);
        }
        __syncthreads();
    }
}

// ---------------- big GEMMs: 0 X1a, 1 X1m, 2 Sa, 3 Sm, 4 Gl ----------------
__global__ void __launch_bounds__(256) gemm_big(int which)
{
    __shared__ __align__(16) __half sA[2 * 128 * SK];
    __shared__ __align__(16) __half sB[2 * 128 * SK];
    const __half *A, *Bw;
    float* C;
    const float* bias = nullptr;
    int lda, ldb, K, ldc;
    const int n0 = blockIdx.x * 128, m0 = blockIdx.y * 128;
    switch (which) {
        case 0: A = g_Xa;        lda = 2048; Bw = g_Wih1a; ldb = 2048; K = 2048; C = g_X1a; ldc = G4; bias = g_bias1a; break;
        case 1: A = g_Xm;        lda = 2048; Bw = g_Wih1m; ldb = 2048; K = 2048; C = g_X1m; ldc = G4; bias = g_bias1m; break;
        case 2: A = g_Hcat;      lda = 2048; Bw = g_Wa;    ldb = HD;   K = HD;   C = g_Sa;  ldc = HD; break;
        case 3: A = g_Hcat + HD; lda = 2048; Bw = g_Wm;    ldb = HD;   K = HD;   C = g_Sm;  ldc = HD; break;
        default:A = g_Hcat;      lda = 2048; Bw = g_Wg;    ldb = 2048; K = 2048; C = g_Gl;  ldc = HD; break;
    }
    float acc[16][4] = {};
    run_gemm<128, 128, 4, 4>(A + (size_t)m0 * lda, lda, Bw, ldb, n0, K, sA, sB, acc);

    const int warp = threadIdx.x >> 5, lane = threadIdx.x & 31;
    const int wm = warp >> 2, wn = warp & 3, grp = lane >> 2, tig = lane & 3;
    #pragma unroll
    for (int mi = 0; mi < 4; mi++)
        #pragma unroll
        for (int ni = 0; ni < 4; ni++) {
            int r = m0 + wm * 64 + mi * 16 + grp;
            int c = n0 + wn * 32 + ni * 8 + tig * 2;
            float b0 = 0.f, b1 = 0.f;
            if (bias) { b0 = bias[c]; b1 = bias[c + 1]; }
            float* p = C + (size_t)r * ldc + c;
            p[0] = acc[mi * 4 + ni][0] + b0;
            p[1] = acc[mi * 4 + ni][1] + b1;
            p = C + (size_t)(r + 8) * ldc + c;
            p[0] = acc[mi * 4 + ni][2] + b0;
            p[1] = acc[mi * 4 + ni][3] + b1;
        }
}

// ---------------- sequential-core GEMM: BM=32, BN in {128,64}, BK=64 -------
// weight row = gate*1024 + u0 + unit; gate = r>>GS, unit = r&((1<<GS)-1).
// BN=128 -> GS=5 (32 units), NI=4.  BN=64 -> GS=4 (16 units), NI=2.
#define BK2  64
#define SK2  72
#define SK2W 36
#define SEQ_SMEM (2*32*SK2*2 + 2*128*SK2*2)   // 9216 + 36864 = 46080 bytes

template<int BN, int NI, int GS>
__device__ __forceinline__ void run_gemm_seq(
    const __half* __restrict__ A,
    const __half* __restrict__ Bw, int u0,
    char* smem_raw, float (*acc)[4])
{
    __half* sA = (__half*)smem_raw;                   // 2 x 32 x SK2
    __half* sB = (__half*)(smem_raw + 2*32*SK2*2);    // 2 x BN x SK2

    const int tid  = threadIdx.x;
    const int warp = tid >> 5, lane = tid & 31;
    const int wm = warp >> 2, wn = warp & 3;
    const int grp = lane >> 2, tig = lane & 3;

    constexpr int TOT = 512 + BN * 16;

    auto load_tile = [&](int kt, int buf) {
        const int k0 = kt * BK2;
        __half* sa = sA + buf * 32 * SK2;
        __half* sb = sB + buf * BN * SK2;
        for (int idx = tid; idx < TOT; idx += 256) {
            if (idx < 512) {
                int r = idx >> 4, c = idx & 15;
                cp8(sa + r * SK2 + c * 4, A + (size_t)r * HD + k0 + c * 4);
            } else {
                int j = idx - 512;
                int r = j >> 4, c = j & 15;
                int wr = ((r >> GS) << 10) + u0 + (r & ((1 << GS) - 1));
                cp8(sb + r * SK2 + c * 4, Bw + (size_t)wr * HD + k0 + c * 4);
            }
        }
        asm volatile("cp.async.commit_group;" ::: "memory");
    };

    const int KT = HD / BK2;   // 16
    load_tile(0, 0);
    for (int kt = 0; kt < KT; kt++) {
        const int buf = kt & 1;
        if (kt + 1 < KT) {
            load_tile(kt + 1, buf ^ 1);
            asm volatile("cp.async.wait_group 1;" ::: "memory");
        } else {
            asm volatile("cp.async.wait_group 0;" ::: "memory");
        }
        __syncthreads();
        const uint32_t* wA = (const uint32_t*)(sA + buf * 32 * SK2);
        const uint32_t* wB = (const uint32_t*)(sB + buf * BN * SK2);
        #pragma unroll
        for (int kk = 0; kk < 4; kk++) {
            uint32_t af[4], bf[NI][2];
            {
                int r = wm * 16 + grp;
                int base = r * SK2W + kk * 8 + tig;
                af[0] = wA[base];
                af[1] = wA[base + 8 * SK2W];
                af[2] = wA[base + 4];
                af[3] = wA[base + 8 * SK2W + 4];
            }
            #pragma unroll
            for (int ni = 0; ni < NI; ni++) {
                int rb = wn * (NI * 8) + ni * 8 + grp;
                int base = rb * SK2W + kk * 8 + tig;
                bf[ni][0] = wB[base];
                bf[ni][1] = wB[base + 4];
            }
            #pragma unroll
            for (int ni = 0; ni < NI; ni++)
                mma16816(acc[ni], af, bf[ni]);
        }
        __syncthreads();
    }
}

template<int BN, int NI>
__device__ __forceinline__ void seq_store_sC(float* sC, float (*acc)[4])
{
    const int warp = threadIdx.x >> 5, lane = threadIdx.x & 31;
    const int wm = warp >> 2, wn = warp & 3, grp = lane >> 2, tig = lane & 3;
    #pragma unroll
    for (int ni = 0; ni < NI; ni++) {
        int r = wm * 16 + grp, c = wn * (NI * 8) + ni * 8 + tig * 2;
        sC[r * BN + c]           = acc[ni][0];  sC[r * BN + c + 1]       = acc[ni][1];
        sC[(r + 8) * BN + c]     = acc[ni][2];  sC[(r + 8) * BN + c + 1] = acc[ni][3];
    }
}

// ---------------- persistent sequential kernel (grid = 128 CTAs) ----------
// Per step: phase1 (4 cells x 32 u-slices, BN=128), gsync,
//           phase2 (2 cells x 64 u-slices, BN=64), gsync.
#define SEQ_CTAS 128

__global__ void __launch_bounds__(256) seq_kernel()
{
    __shared__ __align__(16) char smem_raw[SEQ_SMEM];
    float* sC = (float*)smem_raw;

    const int bx   = blockIdx.x;
    const int cid  = bx >> 5, u0  = (bx & 31) << 5;   // phase 1
    const int cell = bx >> 6, u0p = (bx & 63) << 4;   // phase 2

    for (int t = 0; t < TT; t++) {
        const int rp = t & 1, wp = rp ^ 1;

        // ---------------- phase 1 ----------------
        {
            const __half *A, *Bw;
            switch (cid) {
                case 0:  A = g_h1a[rp]; Bw = g_Whh1a; break;
                case 1:  A = g_h1m[rp]; Bw = g_Whh1m; break;
                case 2:  A = g_h2a;     Bw = g_Whh2a; break;
                default: A = g_h2m;     Bw = g_Whh2m; break;
            }
            float acc[4][4] = {};
            run_gemm_seq<128, 4, 5>(A, Bw, u0, smem_raw, acc);
            seq_store_sC<128, 4>(sC, acc);
            __syncthreads();

            if (cid < 2) {
                const float*  X1 = (cid == 0) ? g_X1a : g_X1m;
                float*        c_ = (cid == 0) ? g_c1a : g_c1m;
                __half*       h_ = (cid == 0) ? g_h1a[wp] : g_h1m[wp];
                for (int idx = threadIdx.x; idx < 32 * 32; idx += 256) {
                    int b = idx >> 5, j = idx & 31, u = u0 + j;
                    size_t xb = ((size_t)(b * 64 + t)) * G4 + u;
                    float i_ = sC[b * 128 + j]      + X1[xb];
                    float f_ = sC[b * 128 + 32 + j] + X1[xb + 1024];
                    float g_ = sC[b * 128 + 64 + j] + X1[xb + 2048];
                    float o_ = sC[b * 128 + 96 + j] + X1[xb + 3072];
                    float cn = sigf(f_) * c_[b * HD + u] + sigf(i_) * tanhf(g_);
                    c_[b * HD + u] = cn;
                    h_[b * HD + u] = __float2half_rn(sigf(o_) * tanhf(cn));
                }
            } else {
                float*       P  = (cid == 2) ? g_part2a : g_part2m;
                const float* bi = (cid == 2) ? g_bias2a : g_bias2m;
                for (int idx = threadIdx.x; idx < 32 * 128; idx += 256) {
                    int b = idx >> 7, n = idx & 127;
                    int col = ((n >> 5) << 10) + u0 + (n & 31);
                    P[b * G4 + col] = sC[b * 128 + n] + bi[col];
                }
            }
        }
        gsync(SEQ_CTAS);

        // ---------------- phase 2 ----------------
        {
            const __half* A2 = (cell == 0) ? g_h1a[wp] : g_h1m[wp];
            const __half* B2 = (cell == 0) ? g_Wih2a   : g_Wih2m;
            float acc2[2][4] = {};
            run_gemm_seq<64, 2, 4>(A2, B2, u0p, smem_raw, acc2);
            seq_store_sC<64, 2>(sC, acc2);
            __syncthreads();

            const float* P  = (cell == 0) ? g_part2a : g_part2m;
            float*       c_ = (cell == 0) ? g_c2a : g_c2m;
            __half*      h_ = (cell == 0) ? g_h2a : g_h2m;
            const int hoff  = (cell == 0) ? 0 : 1024;
            for (int idx = threadIdx.x; idx < 32 * 16; idx += 256) {
                int b = idx >> 4, j = idx & 15, u = u0p + j;
                size_t pb = (size_t)b * G4 + u;
                float i_ = sC[b * 64 + j]      + P[pb];
                float f_ = sC[b * 64 + 16 + j] + P[pb + 1024];
                float g_ = sC[b * 64 + 32 + j] + P[pb + 2048];
                float o_ = sC[b * 64 + 48 + j] + P[pb + 3072];
                float cn = sigf(f_) * c_[b * HD + u] + sigf(i_) * tanhf(g_);
                c_[b * HD + u] = cn;
                __half hv = __float2half_rn(sigf(o_) * tanhf(cn));
                h_[b * HD + u] = hv;
                g_Hcat[(size_t)(b * 64 + t) * 2048 + hoff + u] = hv;
            }
        }
        gsync(SEQ_CTAS);
    }
}

// ---------------- utility kernels ----------------
__global__ void __launch_bounds__(256) f2h_sel_kernel(const float4* __restrict__ src,
                                                      int which, int n4)
{
    __half* dst;
    switch (which) {
        case 0:  dst = g_Xa;    break;
        case 1:  dst = g_Xm;    break;
        case 2:  dst = g_Wih1a; break;
        case 3:  dst = g_Wih1m; break;
        case 4:  dst = g_Whh1a; break;
        case 5:  dst = g_Whh1m; break;
        case 6:  dst = g_Wih2a; break;
        case 7:  dst = g_Wih2m; break;
        case 8:  dst = g_Whh2a; break;
        case 9:  dst = g_Whh2m; break;
        case 10: dst = g_Wg;    break;
        case 11: dst = g_Wa;    break;
        default: dst = g_Wm;    break;
    }
    int i = blockIdx.x * 256 + threadIdx.x;
    if (i < n4) {
        float4 v = src[i];
        __half2 lo = __floats2half2_rn(v.x, v.y);
        __half2 hi = __floats2half2_rn(v.z, v.w);
        uint2 o;
        o.x = *reinterpret_cast<const uint32_t*>(&lo);
        o.y = *reinterpret_cast<const uint32_t*>(&hi);
        reinterpret_cast<uint2*>(dst)[i] = o;
    }
}

__global__ void __launch_bounds__(256) zero_state_kernel()
{
    int i = blockIdx.x * 256 + threadIdx.x;
    if (i < BB * HD) {
        g_h1a[0][i] = __half(0.f); g_h1a[1][i] = __half(0.f);
        g_h1m[0][i] = __half(0.f); g_h1m[1][i] = __half(0.f);
        g_h2a[i] = __half(0.f);    g_h2m[i] = __half(0.f);
        g_c1a[i] = 0.f; g_c1m[i] = 0.f; g_c2a[i] = 0.f; g_c2m[i] = 0.f;
    }
}

__global__ void __launch_bounds__(256) bias_kernel(
    const float* b1a, const float* b1a2, const float* b1m, const float* b1m2,
    const float* b2a, const float* b2a2, const float* b2m, const float* b2m2)
{
    int i = blockIdx.x * 256 + threadIdx.x;
    if (i < G4) {
        g_bias1a[i] = b1a[i] + b1a2[i];
        g_bias1m[i] = b1m[i] + b1m2[i];
        g_bias2a[i] = b2a[i] + b2a2[i];
        g_bias2m[i] = b2m[i] + b2m2[i];
    }
}

__global__ void __launch_bounds__(256) fuse_kernel(
    const float* __restrict__ bg, const float* __restrict__ ba,
    const float* __restrict__ bm, float* __restrict__ out)
{
    int i = blockIdx.x * 256 + threadIdx.x;
    if (i < BT * HD) {
        int h = i & 1023;
        float g = sigf(g_Gl[i] + bg[h]);
        out[i] = g * tanhf(g_Sa[i] + ba[h]) + (1.f - g) * tanhf(g_Sm[i] + bm[h]);
    }
}

// ---------------- host ----------------
extern "C" void kernel_launch(void* const* d_in, const int* in_sizes, int n_in,
                              void* d_out, int out_size)
{
    if (n_in < 24) return;
    const float* in[24];
    for (int i = 0; i < 24; i++) in[i] = (const float*)d_in[i];
    // 0 app, 1 mot, 2-5 1a(Wih,Whh,bih,bhh), 6-9 2a, 10-13 1m, 14-17 2m,
    // 18 Wg, 19 bg, 20 Wa, 21 ba, 22 Wm, 23 bm

    auto f2h = [&](int src, int which, int n) {
        int n4 = n / 4;
        f2h_sel_kernel<<<(n4 + 255) / 256, 256>>>((const float4*)in[src], which, n4);
    };

    // Launch order arranged so ncu's "-s 5 -c 1" profiles gemm_big(0) (6th launch).
    zero_state_kernel<<<(BB * HD + 255) / 256, 256>>>();          // 1
    f2h(0, 0, BT * 2048);                                          // 2  Xa
    f2h(2, 2, G4 * 2048);                                          // 3  Wih1a
    bias_kernel<<<(G4 + 255) / 256, 256>>>(in[4], in[5], in[12], in[13],
                                           in[8], in[9], in[16], in[17]);  // 4
    f2h(1, 1, BT * 2048);                                          // 5  Xm
    gemm_big<<<dim3(32, 16), 256>>>(0);                            // 6  <- PROFILED

    f2h(10, 3, G4 * 2048);   // Wih1m
    f2h(3,  4, G4 * HD);     // Whh1a
    f2h(11, 5, G4 * HD);     // Whh1m
    f2h(6,  6, G4 * HD);     // Wih2a
    f2h(14, 7, G4 * HD);     // Wih2m
    f2h(7,  8, G4 * HD);     // Whh2a
    f2h(15, 9, G4 * HD);     // Whh2m
    f2h(18, 10, HD * 2048);  // Wg
    f2h(20, 11, HD * HD);    // Wa
    f2h(22, 12, HD * HD);    // Wm

    gemm_big<<<dim3(32, 16), 256>>>(1);

    // whole sequential recurrence in ONE persistent kernel
    seq_kernel<<<SEQ_CTAS, 256>>>();

    // fusion GEMMs: M=2048, N=1024
    gemm_big<<<dim3(8, 16), 256>>>(4);
    gemm_big<<<dim3(8, 16), 256>>>(2);
    gemm_big<<<dim3(8, 16), 256>>>(3);

    fuse_kernel<<<(BT * HD + 255) / 256, 256>>>(in[19], in[21], in[23], (float*)d_out);
}